// round 1
// baseline (speedup 1.0000x reference)
#include <cuda_runtime.h>

#define Bn 128
#define Sn 500
#define Dn 32
#define Hn 8
#define HSn 4
#define BHn (Bn*Hn)        // 1024
#define FCIN (Sn*Dn)       // 16000
#define N1 1024
#define KSPLIT 20
#define KSPAN (FCIN/KSPLIT) // 800
#define BKt 16
#define BNt 64
#define NBt (N1/BNt)        // 16

typedef unsigned long long u64;

// ---------------- scratch (no allocation allowed) ----------------
__device__ float g_q[BHn*Sn*HSn];
__device__ float g_k[BHn*Sn*HSn];
__device__ float g_v[BHn*Sn*HSn];
__device__ float g_av[Bn*Sn*Dn];
__device__ float g_flatT[FCIN*Bn];          // [16000][128]
__device__ float g_part[KSPLIT*Bn*N1];      // split-K partials

// ---------------- f32x2 helpers (sm_100+ packed fp32) ----------------
__device__ __forceinline__ u64 pack2(float lo, float hi){ u64 r; asm("mov.b64 %0,{%1,%2};" : "=l"(r) : "f"(lo),"f"(hi)); return r; }
__device__ __forceinline__ void unpack2(u64 v, float& lo, float& hi){ asm("mov.b64 {%0,%1},%2;" : "=f"(lo),"=f"(hi) : "l"(v)); }
__device__ __forceinline__ u64 fma2(u64 a,u64 b,u64 c){ u64 d; asm("fma.rn.f32x2 %0,%1,%2,%3;" : "=l"(d) : "l"(a),"l"(b),"l"(c)); return d; }
__device__ __forceinline__ u64 mul2(u64 a,u64 b){ u64 d; asm("mul.rn.f32x2 %0,%1,%2;" : "=l"(d) : "l"(a),"l"(b)); return d; }
__device__ __forceinline__ u64 add2(u64 a,u64 b){ u64 d; asm("add.rn.f32x2 %0,%1,%2;" : "=l"(d) : "l"(a),"l"(b)); return d; }
__device__ __forceinline__ float ex2f(float x){ float r; asm("ex2.approx.ftz.f32 %0,%1;" : "=f"(r) : "f"(x)); return r; }

#define QSCALE 0.72134752044448169f   // (1/sqrt(4)) * log2(e), folded into q

// ================= K1: QKV projection =================
// grid 8000, 256 thr; 8 rows/block, outputs q (pre-scaled), k, v in [b,h,s,4]
__global__ __launch_bounds__(256) void k_qkv(const float* __restrict__ x,
    const float* __restrict__ Wq, const float* __restrict__ bq,
    const float* __restrict__ Wk, const float* __restrict__ bk,
    const float* __restrict__ Wv, const float* __restrict__ bv)
{
    __shared__ float ws[3*1024];
    __shared__ float bs[3*32];
    __shared__ float xs[8*32];
    int tid = threadIdx.x;
    for(int i=tid;i<1024;i+=256){ ws[i]=Wq[i]; ws[1024+i]=Wk[i]; ws[2048+i]=Wv[i]; }
    if(tid<32){ bs[tid]=bq[tid]; bs[32+tid]=bk[tid]; bs[64+tid]=bv[tid]; }
    int row0 = blockIdx.x*8;
    xs[tid]=x[row0*32+tid];
    __syncthreads();
    #pragma unroll
    for(int t=0;t<3;t++){
        int o = tid + t*256;                 // 0..767
        int row = o/96; int cc = o - row*96;
        int which = cc>>5; int ch = cc&31;
        const float* w  = ws + which*1024 + ch*32;
        const float* xr = xs + row*32;
        float sum = bs[which*32+ch];
        #pragma unroll
        for(int i=0;i<32;i++) sum += xr[i]*w[i];
        int gr = row0+row; int b = gr/Sn; int s = gr - b*Sn;
        int idx = ((b*Hn + (ch>>2))*Sn + s)*HSn + (ch&3);
        if(which==0)      g_q[idx] = sum*QSCALE;
        else if(which==1) g_k[idx] = sum;
        else              g_v[idx] = sum;
    }
}

// ================= K2: attention per (b,h) =================
// 1024 blocks, 128 thr. K,V staged in smem as (f,f) duplicated f32x2 pairs.
// Each thread owns 4 query rows -> two packed-row accumulators -> FFMA2 throughout.
__global__ __launch_bounds__(128) void k_attn()
{
    __shared__ __align__(16) u64 kk[Sn*HSn];
    __shared__ __align__(16) u64 vv[Sn*HSn];
    int tid=threadIdx.x; int bh=blockIdx.x;
    int base = bh*Sn*HSn;
    for(int i=tid;i<Sn*HSn;i+=128){
        float f=g_k[base+i]; kk[i]=pack2(f,f);
        float g=g_v[base+i]; vv[i]=pack2(g,g);
    }
    __syncthreads();
    if(tid<125){
        int r0=tid, r1=tid+125, r2=tid+250, r3=tid+375;
        const float4* q4=(const float4*)(g_q+base);
        float4 qa=q4[r0], qb=q4[r1], qc=q4[r2], qd=q4[r3];
        u64 qp01[4]={pack2(qa.x,qb.x),pack2(qa.y,qb.y),pack2(qa.z,qb.z),pack2(qa.w,qb.w)};
        u64 qp23[4]={pack2(qc.x,qd.x),pack2(qc.y,qd.y),pack2(qc.z,qd.z),pack2(qc.w,qd.w)};
        u64 acc01[4]={0,0,0,0}, acc23[4]={0,0,0,0};
        u64 l01=0, l23=0;
        #pragma unroll 2
        for(int j=0;j<Sn;j++){
            const ulonglong2* kj=(const ulonglong2*)(kk + j*HSn);
            ulonglong2 K0=kj[0], K1=kj[1];
            u64 d01 = mul2(qp01[0],K0.x); d01=fma2(qp01[1],K0.y,d01);
            d01=fma2(qp01[2],K1.x,d01);   d01=fma2(qp01[3],K1.y,d01);
            u64 d23 = mul2(qp23[0],K0.x); d23=fma2(qp23[1],K0.y,d23);
            d23=fma2(qp23[2],K1.x,d23);   d23=fma2(qp23[3],K1.y,d23);
            float s0,s1,s2,s3; unpack2(d01,s0,s1); unpack2(d23,s2,s3);
            u64 p01=pack2(ex2f(s0),ex2f(s1));
            u64 p23=pack2(ex2f(s2),ex2f(s3));
            l01=add2(l01,p01); l23=add2(l23,p23);
            const ulonglong2* vj=(const ulonglong2*)(vv + j*HSn);
            ulonglong2 V0=vj[0], V1=vj[1];
            acc01[0]=fma2(p01,V0.x,acc01[0]); acc01[1]=fma2(p01,V0.y,acc01[1]);
            acc01[2]=fma2(p01,V1.x,acc01[2]); acc01[3]=fma2(p01,V1.y,acc01[3]);
            acc23[0]=fma2(p23,V0.x,acc23[0]); acc23[1]=fma2(p23,V0.y,acc23[1]);
            acc23[2]=fma2(p23,V1.x,acc23[2]); acc23[3]=fma2(p23,V1.y,acc23[3]);
        }
        int b=bh>>3, h=bh&7;
        float l0,l1,l2,l3; unpack2(l01,l0,l1); unpack2(l23,l2,l3);
        float i0=1.f/l0, i1=1.f/l1, i2=1.f/l2, i3=1.f/l3;
        float lo,hi; float4 o0,o1,o2,o3;
        unpack2(acc01[0],lo,hi); o0.x=lo*i0; o1.x=hi*i1;
        unpack2(acc01[1],lo,hi); o0.y=lo*i0; o1.y=hi*i1;
        unpack2(acc01[2],lo,hi); o0.z=lo*i0; o1.z=hi*i1;
        unpack2(acc01[3],lo,hi); o0.w=lo*i0; o1.w=hi*i1;
        unpack2(acc23[0],lo,hi); o2.x=lo*i2; o3.x=hi*i3;
        unpack2(acc23[1],lo,hi); o2.y=lo*i2; o3.y=hi*i3;
        unpack2(acc23[2],lo,hi); o2.z=lo*i2; o3.z=hi*i3;
        unpack2(acc23[3],lo,hi); o2.w=lo*i2; o3.w=hi*i3;
        float* outb = g_av + b*(Sn*Dn) + h*HSn;
        *(float4*)(outb + r0*Dn) = o0;
        *(float4*)(outb + r1*Dn) = o1;
        *(float4*)(outb + r2*Dn) = o2;
        *(float4*)(outb + r3*Dn) = o3;
    }
}

// ================= K3: Wo projection, writes TRANSPOSED flat =================
// grid 500 (one s per block). flatT[(s*32+c)*128 + b] -> coalesced, FC1-friendly.
__global__ __launch_bounds__(256) void k_proj(const float* __restrict__ Wo,
                                              const float* __restrict__ bo)
{
    __shared__ float avs[128*33];   // +1 pad kills 32-way conflicts
    __shared__ float wos[1024];
    __shared__ float bos[32];
    int tid=threadIdx.x; int s=blockIdx.x;
    for(int i=tid;i<1024;i+=256) wos[i]=Wo[i];
    if(tid<32) bos[tid]=bo[tid];
    for(int i=tid;i<4096;i+=256){ int bb=i>>5, c=i&31; avs[bb*33+c]=g_av[bb*(Sn*Dn)+s*Dn+c]; }
    __syncthreads();
    #pragma unroll
    for(int t=0;t<16;t++){
        int o=tid+t*256; int bb=o&127, c=o>>7;
        const float* av=avs+bb*33; const float* w=wos+c*32;
        float sum=bos[c];
        #pragma unroll
        for(int i=0;i<32;i++) sum+=av[i]*w[i];
        g_flatT[(s*32+c)*Bn + bb] = sum;
    }
}

// ================= K4: FC1 split-K GEMM, f32x2 over batch pairs =================
// grid (16 n-blocks, 20 k-splits), 256 thr. Deterministic partials to g_part.
__global__ __launch_bounds__(256) void k_fc1(const float* __restrict__ W1)
{
    __shared__ __align__(16) u64 As[BKt*64];   // [kk][pair] packed (m=2p, 2p+1)
    __shared__ __align__(16) u64 Bs[BKt*64];   // [kk][n]    duplicated (w,w)
    int tid=threadIdx.x;
    int n0=blockIdx.x*BNt, k0=blockIdx.y*KSPAN;
    int tp=tid&15, tn=tid>>4;
    int p0=tp*4, c0=tn*4;
    u64 acc[16];
    #pragma unroll
    for(int i=0;i<16;i++) acc[i]=0;
    const u64* srcA = (const u64*)g_flatT;     // flatT rows contiguous: [k][128] = [k][64 pairs]
    int bn=tid>>2, bk=(tid&3)*4;
    u64 areg[4]; float4 breg;
    {   // prefetch tile 0
        const u64* a = srcA + (size_t)k0*64;
        #pragma unroll
        for(int i=0;i<4;i++) areg[i]=a[tid + i*256];
        breg = *(const float4*)(W1 + (size_t)(n0+bn)*FCIN + k0 + bk);
    }
    const int NT = KSPAN/BKt;  // 50
    for(int t=0;t<NT;t++){
        __syncthreads();
        #pragma unroll
        for(int i=0;i<4;i++) As[tid+i*256]=areg[i];
        Bs[(bk+0)*64+bn]=pack2(breg.x,breg.x);
        Bs[(bk+1)*64+bn]=pack2(breg.y,breg.y);
        Bs[(bk+2)*64+bn]=pack2(breg.z,breg.z);
        Bs[(bk+3)*64+bn]=pack2(breg.w,breg.w);
        __syncthreads();
        if(t+1<NT){
            int k1 = k0 + (t+1)*BKt;
            const u64* a = srcA + (size_t)k1*64;
            #pragma unroll
            for(int i=0;i<4;i++) areg[i]=a[tid+i*256];
            breg = *(const float4*)(W1 + (size_t)(n0+bn)*FCIN + k1 + bk);
        }
        #pragma unroll
        for(int kk=0;kk<BKt;kk++){
            const ulonglong2* ar=(const ulonglong2*)(As + kk*64 + p0);
            ulonglong2 A0=ar[0], A1=ar[1];
            const ulonglong2* br=(const ulonglong2*)(Bs + kk*64 + c0);
            ulonglong2 B0=br[0], B1=br[1];
            u64 a_[4]={A0.x,A0.y,A1.x,A1.y};
            u64 b_[4]={B0.x,B0.y,B1.x,B1.y};
            #pragma unroll
            for(int i=0;i<4;i++)
                #pragma unroll
                for(int j=0;j<4;j++)
                    acc[i*4+j]=fma2(a_[i],b_[j],acc[i*4+j]);
        }
    }
    int ks=blockIdx.y;
    #pragma unroll
    for(int i=0;i<4;i++){
        int m0=2*(p0+i);
        #pragma unroll
        for(int j=0;j<4;j++){
            float lo,hi; unpack2(acc[i*4+j],lo,hi);
            int n=n0+c0+j;
            g_part[((size_t)ks*Bn + m0  )*N1 + n]=lo;
            g_part[((size_t)ks*Bn + m0+1)*N1 + n]=hi;
        }
    }
}

// ================= K5: split-K reduce + FC2 + FC3 =================
// grid 128 (one batch row), 256 thr. Emits out1 [128,64] then out [128,2].
__global__ __launch_bounds__(256) void k_fc23(const float* __restrict__ b1,
    const float* __restrict__ W2, const float* __restrict__ b2,
    const float* __restrict__ W3, const float* __restrict__ b3,
    float* __restrict__ dout)
{
    __shared__ float y1[1024];
    __shared__ float w2s[64*64];       // [kk][o], transposed chunk
    __shared__ float partial[4*64];
    __shared__ float out1s[64];
    int tid=threadIdx.x; int b=blockIdx.x;
    for(int n=tid;n<1024;n+=256){
        float sum=b1[n];
        #pragma unroll
        for(int ks=0;ks<KSPLIT;ks++) sum+=g_part[((size_t)ks*Bn+b)*N1+n];
        y1[n]=sum;
    }
    int o=tid&63, part=tid>>6;
    float acc=0.f;
    for(int chunk=0;chunk<16;chunk++){
        int kbase=chunk*64;
        __syncthreads();   // y1 ready (chunk 0) / prev compute done (chunk>0)
        #pragma unroll
        for(int i=0;i<4;i++){
            int lin=tid+i*256; int row=lin>>4, col4=lin&15;
            float4 f=*(const float4*)(W2 + row*1024 + kbase + col4*4);
            w2s[(col4*4+0)*64+row]=f.x;
            w2s[(col4*4+1)*64+row]=f.y;
            w2s[(col4*4+2)*64+row]=f.z;
            w2s[(col4*4+3)*64+row]=f.w;
        }
        __syncthreads();
        #pragma unroll
        for(int i=0;i<16;i++){
            int k=part*16+i;
            acc += y1[kbase+k]*w2s[k*64+o];
        }
    }
    partial[part*64+o]=acc;
    __syncthreads();
    if(tid<64){
        float v=partial[tid]+partial[64+tid]+partial[128+tid]+partial[192+tid]+b2[tid];
        out1s[tid]=v;
        dout[b*64+tid]=v;
    }
    __syncthreads();
    if(tid<2){
        float s=b3[tid];
        #pragma unroll
        for(int k=0;k<64;k++) s+=out1s[k]*W3[tid*64+k];
        dout[Bn*64 + b*2 + tid]=s;
    }
}

// ================= launch =================
extern "C" void kernel_launch(void* const* d_in, const int* in_sizes, int n_in,
                              void* d_out, int out_size)
{
    const float* x =(const float*)d_in[0];
    const float* Wq=(const float*)d_in[1];  const float* bq=(const float*)d_in[2];
    const float* Wk=(const float*)d_in[3];  const float* bk=(const float*)d_in[4];
    const float* Wv=(const float*)d_in[5];  const float* bv=(const float*)d_in[6];
    const float* Wo=(const float*)d_in[7];  const float* bo=(const float*)d_in[8];
    const float* W1=(const float*)d_in[9];  const float* b1=(const float*)d_in[10];
    const float* W2=(const float*)d_in[11]; const float* b2=(const float*)d_in[12];
    const float* W3=(const float*)d_in[13]; const float* b3=(const float*)d_in[14];
    float* out=(float*)d_out;

    k_qkv <<<(Bn*Sn)/8, 256>>>(x,Wq,bq,Wk,bk,Wv,bv);
    k_attn<<<BHn, 128>>>();
    k_proj<<<Sn, 256>>>(Wo,bo);
    k_fc1 <<<dim3(NBt,KSPLIT), 256>>>(W1);
    k_fc23<<<Bn, 256>>>(b1,W2,b2,W3,b3,out);
}

// round 2
// speedup vs baseline: 1.1771x; 1.1771x over previous
#include <cuda_runtime.h>

#define Bn 128
#define Sn 500
#define Dn 32
#define Hn 8
#define HSn 4
#define BHn (Bn*Hn)        // 1024
#define FCIN (Sn*Dn)       // 16000
#define N1 1024
#define KSPLIT 25
#define KSPAN (FCIN/KSPLIT) // 640
#define BKt 16
#define NT (KSPAN/BKt)      // 40
#define NBt 16              // 1024/64 n-blocks

typedef unsigned long long u64;

// ---------------- scratch (no allocation allowed) ----------------
__device__ float g_q[BHn*Sn*HSn];
__device__ float g_k[BHn*Sn*HSn];
__device__ float g_v[BHn*Sn*HSn];
__device__ float g_av[Bn*Sn*Dn];
__device__ float g_flatT[FCIN*Bn];          // [16000][128]
__device__ float g_part[KSPLIT*Bn*N1];      // split-K partials

// ---------------- f32x2 helpers (sm_100+ packed fp32) ----------------
__device__ __forceinline__ u64 pack2(float lo, float hi){ u64 r; asm("mov.b64 %0,{%1,%2};" : "=l"(r) : "f"(lo),"f"(hi)); return r; }
__device__ __forceinline__ void unpack2(u64 v, float& lo, float& hi){ asm("mov.b64 {%0,%1},%2;" : "=f"(lo),"=f"(hi) : "l"(v)); }
__device__ __forceinline__ u64 fma2(u64 a,u64 b,u64 c){ u64 d; asm("fma.rn.f32x2 %0,%1,%2,%3;" : "=l"(d) : "l"(a),"l"(b),"l"(c)); return d; }
__device__ __forceinline__ u64 mul2(u64 a,u64 b){ u64 d; asm("mul.rn.f32x2 %0,%1,%2;" : "=l"(d) : "l"(a),"l"(b)); return d; }
__device__ __forceinline__ u64 add2(u64 a,u64 b){ u64 d; asm("add.rn.f32x2 %0,%1,%2;" : "=l"(d) : "l"(a),"l"(b)); return d; }
__device__ __forceinline__ float ex2f(float x){ float r; asm("ex2.approx.ftz.f32 %0,%1;" : "=f"(r) : "f"(x)); return r; }
__device__ __forceinline__ unsigned smem_u32(const void* p){ return (unsigned)__cvta_generic_to_shared(p); }
__device__ __forceinline__ void cpasync16(unsigned dst, const void* src){
    asm volatile("cp.async.ca.shared.global [%0], [%1], 16;" :: "r"(dst), "l"(src) : "memory");
}
__device__ __forceinline__ void cpcommit(){ asm volatile("cp.async.commit_group;" ::: "memory"); }
__device__ __forceinline__ void cpwait0(){ asm volatile("cp.async.wait_group 0;" ::: "memory"); }

#define QSCALE 0.72134752044448169f   // (1/sqrt(4)) * log2(e), folded into q

// ================= K1: QKV projection =================
__global__ __launch_bounds__(256) void k_qkv(const float* __restrict__ x,
    const float* __restrict__ Wq, const float* __restrict__ bq,
    const float* __restrict__ Wk, const float* __restrict__ bk,
    const float* __restrict__ Wv, const float* __restrict__ bv)
{
    __shared__ float ws[3*1024];
    __shared__ float bs[3*32];
    __shared__ float xs[8*32];
    int tid = threadIdx.x;
    for(int i=tid;i<1024;i+=256){ ws[i]=Wq[i]; ws[1024+i]=Wk[i]; ws[2048+i]=Wv[i]; }
    if(tid<32){ bs[tid]=bq[tid]; bs[32+tid]=bk[tid]; bs[64+tid]=bv[tid]; }
    int row0 = blockIdx.x*8;
    xs[tid]=x[row0*32+tid];
    __syncthreads();
    #pragma unroll
    for(int t=0;t<3;t++){
        int o = tid + t*256;
        int row = o/96; int cc = o - row*96;
        int which = cc>>5; int ch = cc&31;
        const float* w  = ws + which*1024 + ch*32;
        const float* xr = xs + row*32;
        float sum = bs[which*32+ch];
        #pragma unroll
        for(int i=0;i<32;i++) sum += xr[i]*w[i];
        int gr = row0+row; int b = gr/Sn; int s = gr - b*Sn;
        int idx = ((b*Hn + (ch>>2))*Sn + s)*HSn + (ch&3);
        if(which==0)      g_q[idx] = sum*QSCALE;
        else if(which==1) g_k[idx] = sum;
        else              g_v[idx] = sum;
    }
}

// ================= K2: attention per (b,h) =================
__global__ __launch_bounds__(128) void k_attn()
{
    __shared__ __align__(16) u64 kk[Sn*HSn];
    __shared__ __align__(16) u64 vv[Sn*HSn];
    int tid=threadIdx.x; int bh=blockIdx.x;
    int base = bh*Sn*HSn;
    for(int i=tid;i<Sn*HSn;i+=128){
        float f=g_k[base+i]; kk[i]=pack2(f,f);
        float g=g_v[base+i]; vv[i]=pack2(g,g);
    }
    __syncthreads();
    if(tid<125){
        int r0=tid, r1=tid+125, r2=tid+250, r3=tid+375;
        const float4* q4=(const float4*)(g_q+base);
        float4 qa=q4[r0], qb=q4[r1], qc=q4[r2], qd=q4[r3];
        u64 qp01[4]={pack2(qa.x,qb.x),pack2(qa.y,qb.y),pack2(qa.z,qb.z),pack2(qa.w,qb.w)};
        u64 qp23[4]={pack2(qc.x,qd.x),pack2(qc.y,qd.y),pack2(qc.z,qd.z),pack2(qc.w,qd.w)};
        u64 acc01[4]={0,0,0,0}, acc23[4]={0,0,0,0};
        u64 l01=0, l23=0;
        #pragma unroll 2
        for(int j=0;j<Sn;j++){
            const ulonglong2* kj=(const ulonglong2*)(kk + j*HSn);
            ulonglong2 K0=kj[0], K1=kj[1];
            u64 d01 = mul2(qp01[0],K0.x); d01=fma2(qp01[1],K0.y,d01);
            d01=fma2(qp01[2],K1.x,d01);   d01=fma2(qp01[3],K1.y,d01);
            u64 d23 = mul2(qp23[0],K0.x); d23=fma2(qp23[1],K0.y,d23);
            d23=fma2(qp23[2],K1.x,d23);   d23=fma2(qp23[3],K1.y,d23);
            float s0,s1,s2,s3; unpack2(d01,s0,s1); unpack2(d23,s2,s3);
            u64 p01=pack2(ex2f(s0),ex2f(s1));
            u64 p23=pack2(ex2f(s2),ex2f(s3));
            l01=add2(l01,p01); l23=add2(l23,p23);
            const ulonglong2* vj=(const ulonglong2*)(vv + j*HSn);
            ulonglong2 V0=vj[0], V1=vj[1];
            acc01[0]=fma2(p01,V0.x,acc01[0]); acc01[1]=fma2(p01,V0.y,acc01[1]);
            acc01[2]=fma2(p01,V1.x,acc01[2]); acc01[3]=fma2(p01,V1.y,acc01[3]);
            acc23[0]=fma2(p23,V0.x,acc23[0]); acc23[1]=fma2(p23,V0.y,acc23[1]);
            acc23[2]=fma2(p23,V1.x,acc23[2]); acc23[3]=fma2(p23,V1.y,acc23[3]);
        }
        int b=bh>>3, h=bh&7;
        float l0,l1,l2,l3; unpack2(l01,l0,l1); unpack2(l23,l2,l3);
        float i0=1.f/l0, i1=1.f/l1, i2=1.f/l2, i3=1.f/l3;
        float lo,hi; float4 o0,o1,o2,o3;
        unpack2(acc01[0],lo,hi); o0.x=lo*i0; o1.x=hi*i1;
        unpack2(acc01[1],lo,hi); o0.y=lo*i0; o1.y=hi*i1;
        unpack2(acc01[2],lo,hi); o0.z=lo*i0; o1.z=hi*i1;
        unpack2(acc01[3],lo,hi); o0.w=lo*i0; o1.w=hi*i1;
        unpack2(acc23[0],lo,hi); o2.x=lo*i2; o3.x=hi*i3;
        unpack2(acc23[1],lo,hi); o2.y=lo*i2; o3.y=hi*i3;
        unpack2(acc23[2],lo,hi); o2.z=lo*i2; o3.z=hi*i3;
        unpack2(acc23[3],lo,hi); o2.w=lo*i2; o3.w=hi*i3;
        float* outb = g_av + b*(Sn*Dn) + h*HSn;
        *(float4*)(outb + r0*Dn) = o0;
        *(float4*)(outb + r1*Dn) = o1;
        *(float4*)(outb + r2*Dn) = o2;
        *(float4*)(outb + r3*Dn) = o3;
    }
}

// ================= K3: Wo projection, writes TRANSPOSED flat =================
__global__ __launch_bounds__(256) void k_proj(const float* __restrict__ Wo,
                                              const float* __restrict__ bo)
{
    __shared__ float avs[128*33];
    __shared__ float wos[1024];
    __shared__ float bos[32];
    int tid=threadIdx.x; int s=blockIdx.x;
    for(int i=tid;i<1024;i+=256) wos[i]=Wo[i];
    if(tid<32) bos[tid]=bo[tid];
    for(int i=tid;i<4096;i+=256){ int bb=i>>5, c=i&31; avs[bb*33+c]=g_av[bb*(Sn*Dn)+s*Dn+c]; }
    __syncthreads();
    #pragma unroll
    for(int t=0;t<16;t++){
        int o=tid+t*256; int bb=o&127, c=o>>7;
        const float* av=avs+bb*33; const float* w=wos+c*32;
        float sum=bos[c];
        #pragma unroll
        for(int i=0;i<32;i++) sum+=av[i]*w[i];
        g_flatT[(s*32+c)*Bn + bb] = sum;
    }
}

// ================= K4: FC1 split-K GEMM v2 =================
// grid (16 n-blocks, 25 k-splits) = 400 CTAs (single wave), 128 thr.
// Per CTA: all 64 m-pairs x 64 n. Per thread: 8 pairs x 4 n = 32 FFMA2/kk.
// A via cp.async (tile rows are contiguous in g_flatT), B via reg->dup-u64 smem.
// Double-buffered, ONE syncthreads per tile.
__global__ __launch_bounds__(128,4) void k_fc1(const float* __restrict__ W1)
{
    __shared__ __align__(16) u64 As[2][BKt*64];   // [kk][pair u64]  8KB each
    __shared__ __align__(16) u64 Bs[2][BKt*64];   // [kk][n] dup(w,w) 8KB each
    int tid=threadIdx.x;
    int n0=blockIdx.x*64, k0=blockIdx.y*KSPAN;
    int tp=tid&7, tn=tid>>3;            // 8 m-groups, 16 n-groups
    int c0=tn*4;
    u64 acc[32];
    #pragma unroll
    for(int i=0;i<32;i++) acc[i]=0;

    // A tile t is the contiguous 8KB at g_flatT + (k0+t*16)*128 floats
    const char* aSrcBase = (const char*)g_flatT + (size_t)k0*512;
    unsigned aDst[2] = { smem_u32(As[0]) + (unsigned)tid*16,
                         smem_u32(As[1]) + (unsigned)tid*16 };
    // B: thread covers row n0+bn, 8 floats starting at bk
    int bn=tid>>1, bk=(tid&1)*8;
    const float* wRow = W1 + (size_t)(n0+bn)*FCIN + k0 + bk;

    // prologue: tile 0
    {
        const char* a = aSrcBase;
        #pragma unroll
        for(int j=0;j<4;j++) cpasync16(aDst[0] + j*2048, a + tid*16 + j*2048);
        cpcommit();
        float4 f0 = *(const float4*)(wRow);
        float4 f1 = *(const float4*)(wRow+4);
        u64* B=Bs[0];
        B[(bk+0)*64+bn]=pack2(f0.x,f0.x); B[(bk+1)*64+bn]=pack2(f0.y,f0.y);
        B[(bk+2)*64+bn]=pack2(f0.z,f0.z); B[(bk+3)*64+bn]=pack2(f0.w,f0.w);
        B[(bk+4)*64+bn]=pack2(f1.x,f1.x); B[(bk+5)*64+bn]=pack2(f1.y,f1.y);
        B[(bk+6)*64+bn]=pack2(f1.z,f1.z); B[(bk+7)*64+bn]=pack2(f1.w,f1.w);
    }

    for(int t=0;t<NT;t++){
        cpwait0();
        __syncthreads();
        if(t+1<NT){
            int nb=(t+1)&1;
            const char* a = aSrcBase + (size_t)(t+1)*8192;
            #pragma unroll
            for(int j=0;j<4;j++) cpasync16(aDst[nb] + j*2048, a + tid*16 + j*2048);
            cpcommit();
            const float* w = wRow + (t+1)*BKt;
            float4 f0 = *(const float4*)(w);
            float4 f1 = *(const float4*)(w+4);
            u64* B=Bs[nb];
            B[(bk+0)*64+bn]=pack2(f0.x,f0.x); B[(bk+1)*64+bn]=pack2(f0.y,f0.y);
            B[(bk+2)*64+bn]=pack2(f0.z,f0.z); B[(bk+3)*64+bn]=pack2(f0.w,f0.w);
            B[(bk+4)*64+bn]=pack2(f1.x,f1.x); B[(bk+5)*64+bn]=pack2(f1.y,f1.y);
            B[(bk+6)*64+bn]=pack2(f1.z,f1.z); B[(bk+7)*64+bn]=pack2(f1.w,f1.w);
        }
        const u64* A=As[t&1]; const u64* B=Bs[t&1];
        #pragma unroll
        for(int kkk=0;kkk<BKt;kkk++){
            // A: thread's 8 pairs interleaved: u64 indices tp*2 + i*16 + {0,1}
            const ulonglong2* ap=(const ulonglong2*)(A + kkk*64 + tp*2);
            ulonglong2 A0=ap[0], A1=ap[8], A2=ap[16], A3=ap[24];   // conflict-free: lanes contiguous 16B
            const ulonglong2* bp=(const ulonglong2*)(B + kkk*64 + c0);
            ulonglong2 B0=bp[0], B1=bp[1];
            u64 a_[8]={A0.x,A0.y,A1.x,A1.y,A2.x,A2.y,A3.x,A3.y};
            u64 b_[4]={B0.x,B0.y,B1.x,B1.y};
            #pragma unroll
            for(int i=0;i<8;i++)
                #pragma unroll
                for(int j=0;j<4;j++)
                    acc[i*4+j]=fma2(a_[i],b_[j],acc[i*4+j]);
        }
    }
    // write partials: pair index p(ii) = tp*2 + (ii>>1)*16 + (ii&1)
    int ks=blockIdx.y;
    #pragma unroll
    for(int ii=0;ii<8;ii++){
        int p = tp*2 + (ii>>1)*16 + (ii&1);
        int m0 = 2*p;
        #pragma unroll
        for(int j=0;j<4;j++){
            float lo,hi; unpack2(acc[ii*4+j],lo,hi);
            int n=n0+c0+j;
            g_part[((size_t)ks*Bn + m0  )*N1 + n]=lo;
            g_part[((size_t)ks*Bn + m0+1)*N1 + n]=hi;
        }
    }
}

// ================= K5: split-K reduce + FC2 + FC3 =================
__global__ __launch_bounds__(256) void k_fc23(const float* __restrict__ b1,
    const float* __restrict__ W2, const float* __restrict__ b2,
    const float* __restrict__ W3, const float* __restrict__ b3,
    float* __restrict__ dout)
{
    __shared__ float y1[1024];
    __shared__ float w2s[64*64];
    __shared__ float partial[4*64];
    __shared__ float out1s[64];
    int tid=threadIdx.x; int b=blockIdx.x;
    for(int n=tid;n<1024;n+=256){
        float sum=b1[n];
        #pragma unroll
        for(int ks=0;ks<KSPLIT;ks++) sum+=g_part[((size_t)ks*Bn+b)*N1+n];
        y1[n]=sum;
    }
    int o=tid&63, part=tid>>6;
    float acc=0.f;
    for(int chunk=0;chunk<16;chunk++){
        int kbase=chunk*64;
        __syncthreads();
        #pragma unroll
        for(int i=0;i<4;i++){
            int lin=tid+i*256; int row=lin>>4, col4=lin&15;
            float4 f=*(const float4*)(W2 + row*1024 + kbase + col4*4);
            w2s[(col4*4+0)*64+row]=f.x;
            w2s[(col4*4+1)*64+row]=f.y;
            w2s[(col4*4+2)*64+row]=f.z;
            w2s[(col4*4+3)*64+row]=f.w;
        }
        __syncthreads();
        #pragma unroll
        for(int i=0;i<16;i++){
            int k=part*16+i;
            acc += y1[kbase+k]*w2s[k*64+o];
        }
    }
    partial[part*64+o]=acc;
    __syncthreads();
    if(tid<64){
        float v=partial[tid]+partial[64+tid]+partial[128+tid]+partial[192+tid]+b2[tid];
        out1s[tid]=v;
        dout[b*64+tid]=v;
    }
    __syncthreads();
    if(tid<2){
        float s=b3[tid];
        #pragma unroll
        for(int k=0;k<64;k++) s+=out1s[k]*W3[tid*64+k];
        dout[Bn*64 + b*2 + tid]=s;
    }
}

// ================= launch =================
extern "C" void kernel_launch(void* const* d_in, const int* in_sizes, int n_in,
                              void* d_out, int out_size)
{
    const float* x =(const float*)d_in[0];
    const float* Wq=(const float*)d_in[1];  const float* bq=(const float*)d_in[2];
    const float* Wk=(const float*)d_in[3];  const float* bk=(const float*)d_in[4];
    const float* Wv=(const float*)d_in[5];  const float* bv=(const float*)d_in[6];
    const float* Wo=(const float*)d_in[7];  const float* bo=(const float*)d_in[8];
    const float* W1=(const float*)d_in[9];  const float* b1=(const float*)d_in[10];
    const float* W2=(const float*)d_in[11]; const float* b2=(const float*)d_in[12];
    const float* W3=(const float*)d_in[13]; const float* b3=(const float*)d_in[14];
    float* out=(float*)d_out;

    k_qkv <<<(Bn*Sn)/8, 256>>>(x,Wq,bq,Wk,bk,Wv,bv);
    k_attn<<<BHn, 128>>>();
    k_proj<<<Sn, 256>>>(Wo,bo);
    k_fc1 <<<dim3(NBt,KSPLIT), 256/2>>>(W1);
    k_fc23<<<Bn, 256>>>(b1,W2,b2,W3,b3,out);
}